// round 1
// baseline (speedup 1.0000x reference)
#include <cuda_runtime.h>
#include <math.h>

#define Bz   4
#define NKEY 3136
#define NQ   1568
#define Dm   384
#define Hh   12
#define DH   32
#define BH   (Bz*Hh)     /* 48 */
#define D2   768
#define NP   784         /* nc/2 per batch */

// ---------------- scratch (device globals; allocation-free) ----------------
__device__ float g_xn[(size_t)Bz*NKEY*Dm];   // LN(x)
__device__ float g_cn[(size_t)Bz*NQ*Dm];     // LN(clusters)
__device__ float g_Q [(size_t)BH*NQ*DH];     // [bh][q][dh]
__device__ float g_K [(size_t)BH*NKEY*DH];   // [bh][k][dh]
__device__ float g_V [(size_t)BH*NKEY*DH];   // [bh][k][dh]
__device__ float g_E [(size_t)BH*NQ*NKEY];   // exp(s), 944 MB
__device__ float g_Z [BH*NKEY];              // column sums of exp
__device__ float g_c2[(size_t)Bz*NQ*Dm];     // head-concat attention output
__device__ float g_tsh[BH*NQ];               // per-head token sizes
__device__ float g_y0[(size_t)Bz*NQ*Dm];     // residual + c2@Wo
__device__ float g_yn[(size_t)Bz*NQ*Dm];     // LN768 of y0

// ---------------- utility ----------------
__global__ void zero_kernel(float* p, int n) {
    int i = blockIdx.x * 256 + threadIdx.x;
    if (i < n) p[i] = 0.f;
}

// LayerNorm over last dim d (128 threads per row)
__global__ void ln_kernel(const float* __restrict__ x, const float* __restrict__ g,
                          float* __restrict__ y, int d)
{
    int row = blockIdx.x;
    int tid = threadIdx.x;
    const float* xr = x + (size_t)row * d;
    float s = 0.f, s2 = 0.f;
    for (int i = tid; i < d; i += 128) { float v = xr[i]; s += v; s2 += v * v; }
    __shared__ float sh[64];
    #pragma unroll
    for (int o = 16; o; o >>= 1) {
        s  += __shfl_xor_sync(0xffffffffu, s,  o);
        s2 += __shfl_xor_sync(0xffffffffu, s2, o);
    }
    int w = tid >> 5;
    if ((tid & 31) == 0) { sh[w] = s; sh[32 + w] = s2; }
    __syncthreads();
    if (tid == 0) {
        float a = 0.f, b = 0.f;
        #pragma unroll
        for (int i = 0; i < 4; i++) { a += sh[i]; b += sh[32 + i]; }
        sh[0] = a; sh[32] = b;
    }
    __syncthreads();
    float mu  = sh[0]  / (float)d;
    float var = sh[32] / (float)d - mu * mu;
    float r = rsqrtf(var + 1e-6f);
    float* yr = y + (size_t)row * d;
    for (int i = tid; i < d; i += 128) yr[i] = (xr[i] - mu) * r * g[i];
}

// ---------------- generic fp32 GEMM: 128x128 tile, BK=8, 8x8/thread ----------------
// MODE 0: scatter to g_Q [bh][q][dh]        (A=cn,  B=Wq,   N=384)
// MODE 1: scatter to g_K/g_V [bh][k][dh]    (A=xn,  B=Wkv,  N=768)
// MODE 2: Cout = A@B + res*rscale           (A=c2,  B=Wo,   N=384)
// MODE 3: Cout = A@B                        (A=yn,  B=Wproj,N=768)
template<int MODE>
__global__ void __launch_bounds__(256)
sgemm128(const float* __restrict__ A, const float* __restrict__ Bmat,
         int M, int N, int K,
         const float* __restrict__ res, const float* __restrict__ rscale,
         float* __restrict__ Cout)
{
    __shared__ float As[8][128];
    __shared__ float Bs[8][128];
    const int tid = threadIdx.x;
    const int tx = tid & 15, ty = tid >> 4;
    const int m0 = blockIdx.y * 128, n0 = blockIdx.x * 128;
    const int arow = tid >> 1, acol = (tid & 1) * 4;
    const int brow = tid >> 5, bcol = (tid & 31) * 4;

    float acc[8][8];
    #pragma unroll
    for (int i = 0; i < 8; i++)
        #pragma unroll
        for (int j = 0; j < 8; j++) acc[i][j] = 0.f;

    for (int k0 = 0; k0 < K; k0 += 8) {
        float4 av = make_float4(0.f, 0.f, 0.f, 0.f);
        if (m0 + arow < M)
            av = *reinterpret_cast<const float4*>(A + (size_t)(m0 + arow) * K + k0 + acol);
        As[acol + 0][arow] = av.x; As[acol + 1][arow] = av.y;
        As[acol + 2][arow] = av.z; As[acol + 3][arow] = av.w;
        float4 bv = *reinterpret_cast<const float4*>(Bmat + (size_t)(k0 + brow) * N + n0 + bcol);
        *reinterpret_cast<float4*>(&Bs[brow][bcol]) = bv;
        __syncthreads();
        #pragma unroll
        for (int kk = 0; kk < 8; kk++) {
            float a[8], b[8];
            #pragma unroll
            for (int i = 0; i < 8; i++) a[i] = As[kk][ty + 16 * i];
            #pragma unroll
            for (int j = 0; j < 8; j++) b[j] = Bs[kk][tx + 16 * j];
            #pragma unroll
            for (int i = 0; i < 8; i++)
                #pragma unroll
                for (int j = 0; j < 8; j++)
                    acc[i][j] = fmaf(a[i], b[j], acc[i][j]);
        }
        __syncthreads();
    }

    #pragma unroll
    for (int i = 0; i < 8; i++) {
        int r = m0 + ty + 16 * i;
        if (r >= M) continue;
        #pragma unroll
        for (int j = 0; j < 8; j++) {
            int c = n0 + tx + 16 * j;
            float v = acc[i][j];
            if (MODE == 0) {
                int b = r / NQ, q = r % NQ;
                int hh = c >> 5, di = c & 31;
                g_Q[(((size_t)(b * Hh + hh)) * NQ + q) * DH + di] = v;
            } else if (MODE == 1) {
                int b = r / NKEY, k = r % NKEY;
                int two = c / Dm;
                int hh = (c % Dm) >> 5, di = c & 31;
                float* dst = two ? g_V : g_K;
                dst[(((size_t)(b * Hh + hh)) * NKEY + k) * DH + di] = v;
            } else if (MODE == 2) {
                Cout[(size_t)r * N + c] = v + res[(size_t)r * N + c] * rscale[c];
            } else {
                Cout[(size_t)r * N + c] = v;
            }
        }
    }
}

// ---------------- S = QK^T * scale; E = exp(S); Z[k] += colsum(E) ----------------
// grid: (ceil(NKEY/128), ceil(NQ/128), BH), 256 threads, 8x8 per thread
__global__ void __launch_bounds__(256)
attn_s_kernel()
{
    __shared__ float Qs[32][128];     // [dh][q]
    __shared__ float Ks[32][128];     // [dh][k]
    __shared__ float red[16][128];
    const int tid = threadIdx.x;
    const int tx = tid & 15, ty = tid >> 4;
    const int k0 = blockIdx.x * 128;
    const int q0 = blockIdx.y * 128;
    const int bh = blockIdx.z;

    const float* Qg = g_Q + ((size_t)bh * NQ + q0) * DH;
    const float* Kg = g_K + ((size_t)bh * NKEY + k0) * DH;

    #pragma unroll
    for (int r = 0; r < 4; r++) {
        int lin = (tid + 256 * r) * 4;
        int q = lin >> 5, c = lin & 31;
        float4 v = make_float4(0.f, 0.f, 0.f, 0.f);
        if (q0 + q < NQ) v = *reinterpret_cast<const float4*>(Qg + (size_t)q * DH + c);
        Qs[c + 0][q] = v.x; Qs[c + 1][q] = v.y; Qs[c + 2][q] = v.z; Qs[c + 3][q] = v.w;
    }
    #pragma unroll
    for (int r = 0; r < 4; r++) {
        int lin = (tid + 256 * r) * 4;
        int k = lin >> 5, c = lin & 31;
        float4 v = make_float4(0.f, 0.f, 0.f, 0.f);
        if (k0 + k < NKEY) v = *reinterpret_cast<const float4*>(Kg + (size_t)k * DH + c);
        Ks[c + 0][k] = v.x; Ks[c + 1][k] = v.y; Ks[c + 2][k] = v.z; Ks[c + 3][k] = v.w;
    }
    __syncthreads();

    float acc[8][8];
    #pragma unroll
    for (int i = 0; i < 8; i++)
        #pragma unroll
        for (int j = 0; j < 8; j++) acc[i][j] = 0.f;

    #pragma unroll 4
    for (int kk = 0; kk < 32; kk++) {
        float a[8], b[8];
        #pragma unroll
        for (int i = 0; i < 8; i++) a[i] = Qs[kk][ty + 16 * i];
        #pragma unroll
        for (int j = 0; j < 8; j++) b[j] = Ks[kk][tx + 16 * j];
        #pragma unroll
        for (int i = 0; i < 8; i++)
            #pragma unroll
            for (int j = 0; j < 8; j++)
                acc[i][j] = fmaf(a[i], b[j], acc[i][j]);
    }

    const float scale = 0.17677669529663687f;  // 32^-0.5
    float colp[8];
    #pragma unroll
    for (int j = 0; j < 8; j++) colp[j] = 0.f;

    #pragma unroll
    for (int i = 0; i < 8; i++) {
        int q = q0 + ty + 16 * i;
        bool qv = (q < NQ);
        float* Erow = g_E + ((size_t)bh * NQ + (qv ? q : 0)) * NKEY;
        #pragma unroll
        for (int j = 0; j < 8; j++) {
            float e = __expf(acc[i][j] * scale);
            if (!qv) e = 0.f;
            colp[j] += e;
            int k = k0 + tx + 16 * j;
            if (qv && k < NKEY) Erow[k] = e;
        }
    }
    #pragma unroll
    for (int j = 0; j < 8; j++) red[ty][tx + 16 * j] = colp[j];
    __syncthreads();
    if (tid < 128) {
        float s = 0.f;
        #pragma unroll
        for (int t = 0; t < 16; t++) s += red[t][tid];
        int k = k0 + tid;
        if (k < NKEY) atomicAdd(&g_Z[bh * NKEY + k], s);
    }
}

// ---------------- c2_h = (E/Z) @ V, row-normalized by ts; ts_h stored ----------------
// grid: (ceil(NQ/128), BH), 128 threads; thread: 4 q-rows x 8 dh
__global__ void __launch_bounds__(128)
attn_pv_kernel()
{
    __shared__ float Es[128][36];
    __shared__ float Vs[32][36];
    __shared__ float Zi[32];
    const int tid = threadIdx.x;
    const int tx = tid & 3;    // dh octet: dh = tx*8 + j
    const int ty = tid >> 2;   // 0..31 : q = q0 + ty + 32*i
    const int q0 = blockIdx.x * 128;
    const int bh = blockIdx.y;
    const int b  = bh / Hh, hh = bh % Hh;

    float acc[4][8];
    #pragma unroll
    for (int i = 0; i < 4; i++)
        #pragma unroll
        for (int j = 0; j < 8; j++) acc[i][j] = 0.f;
    float ts[4] = {0.f, 0.f, 0.f, 0.f};

    const float* Ebase = g_E + (size_t)bh * NQ * NKEY;
    const float* Vbase = g_V + (size_t)bh * NKEY * DH;
    const float* Zbase = g_Z + (size_t)bh * NKEY;

    for (int kc = 0; kc < NKEY; kc += 32) {
        #pragma unroll
        for (int r = 0; r < 8; r++) {
            int lin = (tid + 128 * r) * 4;
            int q = lin >> 5, c = lin & 31;
            float4 v = make_float4(0.f, 0.f, 0.f, 0.f);
            if (q0 + q < NQ)
                v = *reinterpret_cast<const float4*>(Ebase + (size_t)(q0 + q) * NKEY + kc + c);
            *reinterpret_cast<float4*>(&Es[q][c]) = v;
        }
        #pragma unroll
        for (int r = 0; r < 2; r++) {
            int lin = (tid + 128 * r) * 4;
            int k = lin >> 5, c = lin & 31;
            float4 v = *reinterpret_cast<const float4*>(Vbase + (size_t)(kc + k) * DH + c);
            *reinterpret_cast<float4*>(&Vs[k][c]) = v;
        }
        if (tid < 32) Zi[tid] = 1.f / Zbase[kc + tid];
        __syncthreads();

        #pragma unroll 4
        for (int kk = 0; kk < 32; kk++) {
            float z = Zi[kk];
            float bv[8];
            #pragma unroll
            for (int j = 0; j < 8; j++) bv[j] = Vs[kk][tx * 8 + j];
            #pragma unroll
            for (int i = 0; i < 4; i++) {
                float e = Es[ty + 32 * i][kk] * z;
                ts[i] += e;
                #pragma unroll
                for (int j = 0; j < 8; j++) acc[i][j] = fmaf(e, bv[j], acc[i][j]);
            }
        }
        __syncthreads();
    }

    #pragma unroll
    for (int i = 0; i < 4; i++) {
        int q = q0 + ty + 32 * i;
        if (q >= NQ) continue;
        float inv = 1.f / (ts[i] + 1e-6f);
        float* dst = g_c2 + ((size_t)b * NQ + q) * Dm + hh * DH + tx * 8;
        #pragma unroll
        for (int j = 0; j < 8; j++) dst[j] = acc[i][j] * inv;
        if (tx == 0) g_tsh[(size_t)bh * NQ + q] = ts[i];
    }
}

// ---------------- token sizes: mean over heads, pair-sum ----------------
__global__ void ts_kernel(float* __restrict__ out)
{
    int idx = blockIdx.x * 256 + threadIdx.x;
    if (idx >= Bz * NP) return;
    int b = idx / NP, p = idx % NP;
    float s = 0.f;
    #pragma unroll
    for (int h = 0; h < Hh; h++) {
        const float* t = g_tsh + ((size_t)(b * Hh + h)) * NQ + 2 * p;
        s += t[0] + t[1];
    }
    out[idx] = s * (1.f / 12.f);
}

// ---------------- launch ----------------
extern "C" void kernel_launch(void* const* d_in, const int* in_sizes, int n_in,
                              void* d_out, int out_size)
{
    const float* x         = (const float*)d_in[0];
    const float* clusters  = (const float*)d_in[1];
    const float* g1        = (const float*)d_in[2];
    const float* Wq        = (const float*)d_in[3];
    const float* Wkv       = (const float*)d_in[4];
    const float* Wo        = (const float*)d_in[5];
    const float* res_scale = (const float*)d_in[6];
    const float* g2        = (const float*)d_in[7];
    const float* Wproj     = (const float*)d_in[8];
    float* out = (float*)d_out;

    float *p_xn, *p_cn, *p_c2, *p_y0, *p_yn, *p_Z;
    cudaGetSymbolAddress((void**)&p_xn, g_xn);
    cudaGetSymbolAddress((void**)&p_cn, g_cn);
    cudaGetSymbolAddress((void**)&p_c2, g_c2);
    cudaGetSymbolAddress((void**)&p_y0, g_y0);
    cudaGetSymbolAddress((void**)&p_yn, g_yn);
    cudaGetSymbolAddress((void**)&p_Z,  g_Z);

    // zero the column-sum accumulator
    zero_kernel<<<(BH * NKEY + 255) / 256, 256>>>(p_Z, BH * NKEY);

    // LayerNorms
    ln_kernel<<<Bz * NKEY, 128>>>(x,        g1, p_xn, Dm);
    ln_kernel<<<Bz * NQ,   128>>>(clusters, g1, p_cn, Dm);

    // projections
    sgemm128<0><<<dim3(3, 49),  256>>>(p_cn, Wq,  Bz * NQ,   Dm,     Dm, nullptr, nullptr, nullptr);
    sgemm128<1><<<dim3(6, 98),  256>>>(p_xn, Wkv, Bz * NKEY, 2 * Dm, Dm, nullptr, nullptr, nullptr);

    // attention: E = exp(QK^T*scale), Z column sums
    attn_s_kernel<<<dim3(25, 13, BH), 256>>>();
    // c2 = normalize(E/Z) @ V, token sizes
    attn_pv_kernel<<<dim3(13, BH), 128>>>();

    // output stage
    sgemm128<2><<<dim3(3, 49), 256>>>(p_c2, Wo, Bz * NQ, Dm, Dm, clusters, res_scale, p_y0);
    ln_kernel<<<Bz * NP, 128>>>(p_y0, g2, p_yn, D2);
    sgemm128<3><<<dim3(6, 25), 256>>>(p_yn, Wproj, Bz * NP, D2, D2, nullptr, nullptr, out);

    // token sizes output
    ts_kernel<<<(Bz * NP + 255) / 256, 256>>>(out + (size_t)Bz * NP * D2);
}

// round 2
// speedup vs baseline: 2.9967x; 2.9967x over previous
#include <cuda_runtime.h>
#include <cuda_bf16.h>
#include <math.h>

#define Bz   4
#define NKEY 3136
#define NQ   1568
#define Dm   384
#define Hh   12
#define DH   32
#define BH   (Bz*Hh)
#define D2   768
#define NP   784
#define NKP  3200           /* NKEY padded to 128 multiple */
#define SM_SCALE 0.17677669529663687f

typedef __nv_bfloat16 bf16;

// ---------------- scratch ----------------
__device__ bf16  g_xnb[(size_t)Bz*NKEY*Dm];
__device__ bf16  g_cnb[(size_t)Bz*NQ*Dm];
__device__ bf16  g_Wqb[Dm*Dm];
__device__ bf16  g_Wkvb[Dm*2*Dm];
__device__ bf16  g_Qb[(size_t)BH*NQ*DH];     // pre-scaled by SM_SCALE
__device__ bf16  g_Kb[(size_t)BH*NKEY*DH];
__device__ bf16  g_Vb[(size_t)BH*NKEY*DH];
__device__ bf16  g_Vp[(size_t)BH*NKP*40];    // [V/Z | 1/Z | 0-pad]
__device__ float g_c2[(size_t)Bz*NQ*Dm];
__device__ float g_tsh[BH*NQ];
__device__ float g_y0[(size_t)Bz*NQ*Dm];
__device__ float g_yn[(size_t)Bz*NQ*Dm];

// ---------------- mma helpers ----------------
__device__ __forceinline__ unsigned sm_addr(const void* p) {
    return (unsigned)__cvta_generic_to_shared(p);
}
__device__ __forceinline__ void ldsm4(unsigned r[4], const bf16* p) {
    unsigned a = sm_addr(p);
    asm volatile("ldmatrix.sync.aligned.m8n8.x4.shared.b16 {%0,%1,%2,%3},[%4];\n"
        : "=r"(r[0]),"=r"(r[1]),"=r"(r[2]),"=r"(r[3]) : "r"(a));
}
__device__ __forceinline__ void ldsm4t(unsigned r[4], const bf16* p) {
    unsigned a = sm_addr(p);
    asm volatile("ldmatrix.sync.aligned.m8n8.x4.trans.shared.b16 {%0,%1,%2,%3},[%4];\n"
        : "=r"(r[0]),"=r"(r[1]),"=r"(r[2]),"=r"(r[3]) : "r"(a));
}
__device__ __forceinline__ void ldsm2t(unsigned r[2], const bf16* p) {
    unsigned a = sm_addr(p);
    asm volatile("ldmatrix.sync.aligned.m8n8.x2.trans.shared.b16 {%0,%1},[%2];\n"
        : "=r"(r[0]),"=r"(r[1]) : "r"(a));
}
__device__ __forceinline__ void mma_bf16(float c[4], const unsigned a[4], unsigned b0, unsigned b1) {
    asm volatile("mma.sync.aligned.m16n8k16.row.col.f32.bf16.bf16.f32 "
        "{%0,%1,%2,%3},{%4,%5,%6,%7},{%8,%9},{%0,%1,%2,%3};\n"
        : "+f"(c[0]),"+f"(c[1]),"+f"(c[2]),"+f"(c[3])
        : "r"(a[0]),"r"(a[1]),"r"(a[2]),"r"(a[3]),"r"(b0),"r"(b1));
}
__device__ __forceinline__ unsigned packbf(float a, float b) {
    __nv_bfloat162 h = __floats2bfloat162_rn(a, b);
    return *reinterpret_cast<unsigned*>(&h);
}
// per-lane ldmatrix base: covers 16 rows x 16 cols (or x2 variants)
__device__ __forceinline__ const bf16* lm(const bf16* base, int lane, int stride) {
    return base + (lane & 15) * stride + (lane >> 4) * 8;
}

// ---------------- small utils ----------------
__global__ void cvt_kernel(const float* __restrict__ s, bf16* __restrict__ d, int n) {
    int i = blockIdx.x * 256 + threadIdx.x;
    if (i < n) d[i] = __float2bfloat16(s[i]);
}

template<typename OT>
__global__ void ln_kernel(const float* __restrict__ x, const float* __restrict__ g,
                          OT* __restrict__ y, int d)
{
    int row = blockIdx.x;
    int tid = threadIdx.x;
    const float* xr = x + (size_t)row * d;
    float s = 0.f, s2 = 0.f;
    for (int i = tid; i < d; i += 128) { float v = xr[i]; s += v; s2 += v * v; }
    __shared__ float sh[64];
    #pragma unroll
    for (int o = 16; o; o >>= 1) {
        s  += __shfl_xor_sync(0xffffffffu, s,  o);
        s2 += __shfl_xor_sync(0xffffffffu, s2, o);
    }
    int w = tid >> 5;
    if ((tid & 31) == 0) { sh[w] = s; sh[32 + w] = s2; }
    __syncthreads();
    if (tid == 0) {
        float a = 0.f, b = 0.f;
        #pragma unroll
        for (int i = 0; i < 4; i++) { a += sh[i]; b += sh[32 + i]; }
        sh[0] = a; sh[32] = b;
    }
    __syncthreads();
    float mu  = sh[0]  / (float)d;
    float var = sh[32] / (float)d - mu * mu;
    float r = rsqrtf(var + 1e-6f);
    OT* yr = y + (size_t)row * d;
    for (int i = tid; i < d; i += 128) yr[i] = (OT)((xr[i] - mu) * r * g[i]);
}

// ---------------- bf16 HMMA projection GEMM: 128x128 tile, k-step 32 ----------------
// MODE 0: scatter Q (pre-scaled)   MODE 1: scatter K/V
template<int MODE>
__global__ void __launch_bounds__(256)
bgemm(const bf16* __restrict__ A, const bf16* __restrict__ Bm, int M, int N, int K)
{
    __shared__ bf16 As[128 * 40];
    __shared__ bf16 Bs[32 * 136];
    const int tid = threadIdx.x;
    const int w = tid >> 5, lane = tid & 31;
    const int wm = w >> 1, wn = w & 1;          // 4x2 warp grid: 32 rows x 64 cols each
    const int m0 = blockIdx.y * 128, n0 = blockIdx.x * 128;

    float acc[2][8][4];
    #pragma unroll
    for (int i = 0; i < 2; i++)
        #pragma unroll
        for (int j = 0; j < 8; j++)
            #pragma unroll
            for (int t = 0; t < 4; t++) acc[i][j][t] = 0.f;

    for (int k0 = 0; k0 < K; k0 += 32) {
        #pragma unroll
        for (int i = 0; i < 2; i++) {
            int idx = tid + 256 * i;
            int row = idx >> 2, col = (idx & 3) * 8;
            uint4 v = *reinterpret_cast<const uint4*>(A + (size_t)(m0 + row) * K + k0 + col);
            *reinterpret_cast<uint4*>(&As[row * 40 + col]) = v;
        }
        #pragma unroll
        for (int i = 0; i < 2; i++) {
            int idx = tid + 256 * i;
            int row = idx >> 4, col = (idx & 15) * 8;
            uint4 v = *reinterpret_cast<const uint4*>(Bm + (size_t)(k0 + row) * N + n0 + col);
            *reinterpret_cast<uint4*>(&Bs[row * 136 + col]) = v;
        }
        __syncthreads();
        #pragma unroll
        for (int kc = 0; kc < 2; kc++) {
            unsigned af[2][4];
            ldsm4(af[0], lm(&As[(wm * 32 + 0)  * 40 + kc * 16], lane, 40));
            ldsm4(af[1], lm(&As[(wm * 32 + 16) * 40 + kc * 16], lane, 40));
            #pragma unroll
            for (int p = 0; p < 4; p++) {
                unsigned bf[4];
                ldsm4t(bf, lm(&Bs[(kc * 16) * 136 + wn * 64 + p * 16], lane, 136));
                #pragma unroll
                for (int mt = 0; mt < 2; mt++) {
                    mma_bf16(acc[mt][2 * p + 0], af[mt], bf[0], bf[1]);
                    mma_bf16(acc[mt][2 * p + 1], af[mt], bf[2], bf[3]);
                }
            }
        }
        __syncthreads();
    }

    #pragma unroll
    for (int mt = 0; mt < 2; mt++) {
        #pragma unroll
        for (int half = 0; half < 2; half++) {
            int gr = m0 + wm * 32 + mt * 16 + (lane >> 2) + half * 8;
            #pragma unroll
            for (int nb = 0; nb < 8; nb++) {
                int gc = n0 + wn * 64 + nb * 8 + (lane & 3) * 2;
                float v0 = acc[mt][nb][half * 2 + 0];
                float v1 = acc[mt][nb][half * 2 + 1];
                if (MODE == 0) {
                    int b = gr / NQ, q = gr - b * NQ;
                    int hh = gc >> 5, di = gc & 31;
                    __nv_bfloat162 hv = __floats2bfloat162_rn(v0 * SM_SCALE, v1 * SM_SCALE);
                    *reinterpret_cast<__nv_bfloat162*>(
                        &g_Qb[(((size_t)(b * Hh + hh)) * NQ + q) * DH + di]) = hv;
                } else {
                    int b = gr / NKEY, k = gr - b * NKEY;
                    int two = gc >= Dm;
                    int cc = gc - two * Dm;
                    int hh = cc >> 5, di = cc & 31;
                    bf16* dst = two ? g_Vb : g_Kb;
                    __nv_bfloat162 hv = __floats2bfloat162_rn(v0, v1);
                    *reinterpret_cast<__nv_bfloat162*>(
                        &dst[(((size_t)(b * Hh + hh)) * NKEY + k) * DH + di]) = hv;
                }
            }
        }
    }
}

// ---------------- Z-pass: Z[k]=sum_q exp(s), build V'' = [V/Z | 1/Z | 0] ----------------
// grid (25, BH), 256 threads. CTA owns a 128-key tile; sweeps all queries.
__global__ void __launch_bounds__(256)
zpass()
{
    __shared__ bf16 Ks[128 * 40];
    __shared__ bf16 Qs[128 * 40];
    __shared__ float zsh[128];
    const int tid = threadIdx.x;
    const int w = tid >> 5, lane = tid & 31;
    const int k0 = blockIdx.x * 128;
    const int bh = blockIdx.y;

    #pragma unroll
    for (int i = 0; i < 2; i++) {
        int idx = tid + 256 * i;
        int row = idx >> 2, col = (idx & 3) * 8;
        uint4 v = make_uint4(0, 0, 0, 0);
        int kg = k0 + row;
        if (kg < NKEY) v = *reinterpret_cast<const uint4*>(&g_Kb[((size_t)bh * NKEY + kg) * DH + col]);
        *reinterpret_cast<uint4*>(&Ks[row * 40 + col]) = v;
    }
    __syncthreads();

    unsigned aK[2][4];   // A = K rows (16 per warp), kdim = dh
    ldsm4(aK[0], lm(&Ks[(w * 16) * 40 + 0],  lane, 40));
    ldsm4(aK[1], lm(&Ks[(w * 16) * 40 + 16], lane, 40));

    float zacc[2] = {0.f, 0.f};

    for (int qc = 0; qc < 13; qc++) {
        __syncthreads();
        int q0 = qc * 128;
        #pragma unroll
        for (int i = 0; i < 2; i++) {
            int idx = tid + 256 * i;
            int row = idx >> 2, col = (idx & 3) * 8;
            uint4 v = make_uint4(0, 0, 0, 0);
            int qg = q0 + row;
            if (qg < NQ) v = *reinterpret_cast<const uint4*>(&g_Qb[((size_t)bh * NQ + qg) * DH + col]);
            *reinterpret_cast<uint4*>(&Qs[row * 40 + col]) = v;
        }
        __syncthreads();
        #pragma unroll
        for (int nb2 = 0; nb2 < 8; nb2++) {
            unsigned bA[4], bB[4];
            ldsm4(bA, lm(&Qs[(nb2 * 16) * 40 + 0],  lane, 40));
            ldsm4(bB, lm(&Qs[(nb2 * 16) * 40 + 16], lane, 40));
            #pragma unroll
            for (int s = 0; s < 2; s++) {
                float c[4] = {0.f, 0.f, 0.f, 0.f};
                mma_bf16(c, aK[0], bA[s], bA[s + 2]);
                mma_bf16(c, aK[1], bB[s], bB[s + 2]);
                #pragma unroll
                for (int j = 0; j < 4; j++) {
                    int col = nb2 * 16 + s * 8 + (lane & 3) * 2 + (j & 1);
                    if (q0 + col < NQ) zacc[j >> 1] += __expf(c[j]);
                }
            }
        }
    }

    #pragma unroll
    for (int i = 0; i < 2; i++) {
        zacc[i] += __shfl_xor_sync(0xffffffffu, zacc[i], 1);
        zacc[i] += __shfl_xor_sync(0xffffffffu, zacc[i], 2);
    }
    if ((lane & 3) == 0) {
        zsh[w * 16 + (lane >> 2)]     = zacc[0];
        zsh[w * 16 + 8 + (lane >> 2)] = zacc[1];
    }
    __syncthreads();

    if (tid < 128) {
        int kg = k0 + tid;
        bf16 outr[40];
        if (kg < NKEY) {
            float iz = 1.f / zsh[tid];
            const bf16* vr = &g_Vb[((size_t)bh * NKEY + kg) * DH];
            #pragma unroll
            for (int j = 0; j < 32; j++) outr[j] = __float2bfloat16(__bfloat162float(vr[j]) * iz);
            outr[32] = __float2bfloat16(iz);
            #pragma unroll
            for (int j = 33; j < 40; j++) outr[j] = __float2bfloat16(0.f);
        } else {
            #pragma unroll
            for (int j = 0; j < 40; j++) outr[j] = __float2bfloat16(0.f);
        }
        bf16* dst = &g_Vp[((size_t)bh * NKP + k0 + tid) * 40];
        #pragma unroll
        for (int j = 0; j < 5; j++)
            *reinterpret_cast<uint4*>(dst + j * 8) = *reinterpret_cast<const uint4*>(outr + j * 8);
    }
}

// ---------------- PV-pass: c2 = (E @ V'')/(ts+eps), ts = E @ invZ ----------------
// grid (13, BH), 256 threads. CTA owns a 128-query tile; sweeps all keys.
__global__ void __launch_bounds__(256)
pvpass()
{
    __shared__ bf16 Qs[128 * 40];
    __shared__ bf16 Ks[128 * 40];
    __shared__ bf16 Vs[128 * 40];
    const int tid = threadIdx.x;
    const int w = tid >> 5, lane = tid & 31;
    const int q0 = blockIdx.x * 128;
    const int bh = blockIdx.y;
    const int b = bh / Hh, hh = bh % Hh;

    #pragma unroll
    for (int i = 0; i < 2; i++) {
        int idx = tid + 256 * i;
        int row = idx >> 2, col = (idx & 3) * 8;
        uint4 v = make_uint4(0, 0, 0, 0);
        int qg = q0 + row;
        if (qg < NQ) v = *reinterpret_cast<const uint4*>(&g_Qb[((size_t)bh * NQ + qg) * DH + col]);
        *reinterpret_cast<uint4*>(&Qs[row * 40 + col]) = v;
    }
    __syncthreads();

    unsigned aQ[2][4];
    ldsm4(aQ[0], lm(&Qs[(w * 16) * 40 + 0],  lane, 40));
    ldsm4(aQ[1], lm(&Qs[(w * 16) * 40 + 16], lane, 40));

    float acc[5][4];
    #pragma unroll
    for (int i = 0; i < 5; i++)
        #pragma unroll
        for (int t = 0; t < 4; t++) acc[i][t] = 0.f;

    for (int kt = 0; kt < 25; kt++) {
        int k0 = kt * 128;
        __syncthreads();
        #pragma unroll
        for (int i = 0; i < 2; i++) {
            int idx = tid + 256 * i;
            int row = idx >> 2, col = (idx & 3) * 8;
            uint4 v = make_uint4(0, 0, 0, 0);
            int kg = k0 + row;
            if (kg < NKEY) v = *reinterpret_cast<const uint4*>(&g_Kb[((size_t)bh * NKEY + kg) * DH + col]);
            *reinterpret_cast<uint4*>(&Ks[row * 40 + col]) = v;
        }
        #pragma unroll
        for (int i = 0; i < 3; i++) {
            int idx = tid + 256 * i;
            if (idx < 640) {
                int row = idx / 5, col = (idx % 5) * 8;
                uint4 v = *reinterpret_cast<const uint4*>(&g_Vp[((size_t)bh * NKP + k0 + row) * 40 + col]);
                *reinterpret_cast<uint4*>(&Vs[row * 40 + col]) = v;
            }
        }
        __syncthreads();

        unsigned pa[8][4];
        #pragma unroll
        for (int nb2 = 0; nb2 < 8; nb2++) {
            unsigned bA[4], bB[4];
            ldsm4(bA, lm(&Ks[(nb2 * 16) * 40 + 0],  lane, 40));
            ldsm4(bB, lm(&Ks[(nb2 * 16) * 40 + 16], lane, 40));
            float c0[4] = {0.f, 0.f, 0.f, 0.f};
            float c1[4] = {0.f, 0.f, 0.f, 0.f};
            mma_bf16(c0, aQ[0], bA[0], bA[2]);
            mma_bf16(c0, aQ[1], bB[0], bB[2]);
            mma_bf16(c1, aQ[0], bA[1], bA[3]);
            mma_bf16(c1, aQ[1], bB[1], bB[3]);
            float e00 = __expf(c0[0]), e01 = __expf(c0[1]), e02 = __expf(c0[2]), e03 = __expf(c0[3]);
            float e10 = __expf(c1[0]), e11 = __expf(c1[1]), e12 = __expf(c1[2]), e13 = __expf(c1[3]);
            pa[nb2][0] = packbf(e00, e01);
            pa[nb2][1] = packbf(e02, e03);
            pa[nb2][2] = packbf(e10, e11);
            pa[nb2][3] = packbf(e12, e13);
        }
        #pragma unroll
        for (int kc = 0; kc < 8; kc++) {
            unsigned v0[4], v1[4], v2[2];
            ldsm4t(v0, lm(&Vs[(kc * 16) * 40 + 0],  lane, 40));
            ldsm4t(v1, lm(&Vs[(kc * 16) * 40 + 16], lane, 40));
            ldsm2t(v2, lm(&Vs[(kc * 16) * 40 + 32], lane, 40));
            mma_bf16(acc[0], pa[kc], v0[0], v0[1]);
            mma_bf16(acc[1], pa[kc], v0[2], v0[3]);
            mma_bf16(acc[2], pa[kc], v1[0], v1[1]);
            mma_bf16(acc[3], pa[kc], v1[2], v1[3]);
            mma_bf16(acc[4], pa[kc], v2[0], v2[1]);
        }
    }

    // ts broadcast within quad (col 32 lives at lanes with (lane&3)==0)
    int src = lane & 28;
    float den0 = __shfl_sync(0xffffffffu, acc[4][0], src);
    float den1 = __shfl_sync(0xffffffffu, acc[4][2], src);
    float inv0 = 1.f / (den0 + 1e-6f);
    float inv1 = 1.f / (den1 + 1e-6f);

    int qr0 = q0 + w * 16 + (lane >> 2);
    int qr1 = qr0 + 8;
    if (qr0 < NQ) {
        float* dst = &g_c2[((size_t)b * NQ + qr0) * Dm + hh * DH + (lane & 3) * 2];
        #pragma unroll
        for (int nb = 0; nb < 4; nb++)
            *reinterpret_cast<float2*>(dst + nb * 8) = make_float2(acc[nb][0] * inv0, acc[nb][1] * inv0);
        if ((lane & 3) == 0) g_tsh[(size_t)bh * NQ + qr0] = den0;
    }
    if (qr1 < NQ) {
        float* dst = &g_c2[((size_t)b * NQ + qr1) * Dm + hh * DH + (lane & 3) * 2];
        #pragma unroll
        for (int nb = 0; nb < 4; nb++)
            *reinterpret_cast<float2*>(dst + nb * 8) = make_float2(acc[nb][2] * inv1, acc[nb][3] * inv1);
        if ((lane & 3) == 0) g_tsh[(size_t)bh * NQ + qr1] = den1;
    }
}

// ---------------- fp32 SIMT GEMM for the output path (unchanged) ----------------
// MODE 2: Cout = A@B + res*rscale   MODE 3: Cout = A@B
template<int MODE>
__global__ void __launch_bounds__(256)
sgemm128(const float* __restrict__ A, const float* __restrict__ Bmat,
         int M, int N, int K,
         const float* __restrict__ res, const float* __restrict__ rscale,
         float* __restrict__ Cout)
{
    __shared__ float As[8][128];
    __shared__ float Bs[8][128];
    const int tid = threadIdx.x;
    const int tx = tid & 15, ty = tid >> 4;
    const int m0 = blockIdx.y * 128, n0 = blockIdx.x * 128;
    const int arow = tid >> 1, acol = (tid & 1) * 4;
    const int brow = tid >> 5, bcol = (tid & 31) * 4;

    float acc[8][8];
    #pragma unroll
    for (int i = 0; i < 8; i++)
        #pragma unroll
        for (int j = 0; j < 8; j++) acc[i][j] = 0.f;

    for (int k0 = 0; k0 < K; k0 += 8) {
        float4 av = make_float4(0.f, 0.f, 0.f, 0.f);
        if (m0 + arow < M)
            av = *reinterpret_cast<const float4*>(A + (size_t)(m0 + arow) * K + k0 + acol);
        As[acol + 0][arow] = av.x; As[acol + 1][arow] = av.y;
        As[acol + 2][arow] = av.z; As[acol + 3][arow] = av.w;
        float4 bv = *reinterpret_cast<const float4*>(Bmat + (size_t)(k0 + brow) * N + n0 + bcol);
        *reinterpret_cast<float4*>(&Bs[brow][bcol]) = bv;
        __syncthreads();
        #pragma unroll
        for (int kk = 0; kk < 8; kk++) {
            float a[8], bb[8];
            #pragma unroll
            for (int i = 0; i < 8; i++) a[i] = As[kk][ty + 16 * i];
            #pragma unroll
            for (int j = 0; j < 8; j++) bb[j] = Bs[kk][tx + 16 * j];
            #pragma unroll
            for (int i = 0; i < 8; i++)
                #pragma unroll
                for (int j = 0; j < 8; j++)
                    acc[i][j] = fmaf(a[i], bb[j], acc[i][j]);
        }
        __syncthreads();
    }

    #pragma unroll
    for (int i = 0; i < 8; i++) {
        int r = m0 + ty + 16 * i;
        if (r >= M) continue;
        #pragma unroll
        for (int j = 0; j < 8; j++) {
            int c = n0 + tx + 16 * j;
            float v = acc[i][j];
            if (MODE == 2) {
                Cout[(size_t)r * N + c] = v + res[(size_t)r * N + c] * rscale[c];
            } else {
                Cout[(size_t)r * N + c] = v;
            }
        }
    }
}

// ---------------- token sizes output ----------------
__global__ void ts_kernel(float* __restrict__ out)
{
    int idx = blockIdx.x * 256 + threadIdx.x;
    if (idx >= Bz * NP) return;
    int b = idx / NP, p = idx % NP;
    float s = 0.f;
    #pragma unroll
    for (int h = 0; h < Hh; h++) {
        const float* t = g_tsh + ((size_t)(b * Hh + h)) * NQ + 2 * p;
        s += t[0] + t[1];
    }
    out[idx] = s * (1.f / 12.f);
}

// ---------------- launch ----------------
extern "C" void kernel_launch(void* const* d_in, const int* in_sizes, int n_in,
                              void* d_out, int out_size)
{
    const float* x         = (const float*)d_in[0];
    const float* clusters  = (const float*)d_in[1];
    const float* g1        = (const float*)d_in[2];
    const float* Wq        = (const float*)d_in[3];
    const float* Wkv       = (const float*)d_in[4];
    const float* Wo        = (const float*)d_in[5];
    const float* res_scale = (const float*)d_in[6];
    const float* g2        = (const float*)d_in[7];
    const float* Wproj     = (const float*)d_in[8];
    float* out = (float*)d_out;

    bf16 *p_xnb, *p_cnb, *p_Wqb, *p_Wkvb;
    float *p_c2, *p_y0, *p_yn;
    cudaGetSymbolAddress((void**)&p_xnb, g_xnb);
    cudaGetSymbolAddress((void**)&p_cnb, g_cnb);
    cudaGetSymbolAddress((void**)&p_Wqb, g_Wqb);
    cudaGetSymbolAddress((void**)&p_Wkvb, g_Wkvb);
    cudaGetSymbolAddress((void**)&p_c2, g_c2);
    cudaGetSymbolAddress((void**)&p_y0, g_y0);
    cudaGetSymbolAddress((void**)&p_yn, g_yn);

    // weight conversion
    cvt_kernel<<<(Dm * Dm + 255) / 256, 256>>>(Wq, p_Wqb, Dm * Dm);
    cvt_kernel<<<(Dm * 2 * Dm + 255) / 256, 256>>>(Wkv, p_Wkvb, Dm * 2 * Dm);

    // LayerNorms (bf16 outputs feed HMMA projections)
    ln_kernel<bf16><<<Bz * NKEY, 128>>>(x,        g1, p_xnb, Dm);
    ln_kernel<bf16><<<Bz * NQ,   128>>>(clusters, g1, p_cnb, Dm);

    // projections (bf16 tensor core)
    bgemm<0><<<dim3(3, 49), 256>>>(p_cnb, p_Wqb,  Bz * NQ,   Dm,     Dm);
    bgemm<1><<<dim3(6, 98), 256>>>(p_xnb, p_Wkvb, Bz * NKEY, 2 * Dm, Dm);

    // attention
    zpass<<<dim3(25, BH), 256>>>();
    pvpass<<<dim3(13, BH), 256>>>();

    // output path (fp32 for precision)
    sgemm128<2><<<dim3(3, 49), 256>>>(p_c2, Wo, Bz * NQ, Dm, Dm, clusters, res_scale, p_y0);
    ln_kernel<float><<<Bz * NP, 128>>>(p_y0, g2, p_yn, D2);
    sgemm128<3><<<dim3(6, 25), 256>>>(p_yn, Wproj, Bz * NP, D2, D2, nullptr, nullptr, out);

    ts_kernel<<<(Bz * NP + 255) / 256, 256>>>(out + (size_t)Bz * NP * D2);
}

// round 3
// speedup vs baseline: 4.3118x; 1.4388x over previous
#include <cuda_runtime.h>
#include <cuda_bf16.h>
#include <math.h>

#define Bz   4
#define NKEY 3136
#define NQ   1568
#define Dm   384
#define Hh   12
#define DH   32
#define BH   (Bz*Hh)
#define D2   768
#define NP   784
#define NKP  3200
#define SM_SCALE 0.17677669529663687f
#define LOG2E    1.4426950408889634f

typedef __nv_bfloat16 bf16;

// ---------------- scratch ----------------
__device__ bf16  g_xnb[(size_t)Bz*NKEY*Dm];
__device__ bf16  g_cnb[(size_t)Bz*NQ*Dm];
__device__ bf16  g_Wqb[Dm*Dm];
__device__ bf16  g_Wkvb[Dm*2*Dm];
__device__ bf16  g_Woh[Dm*Dm];
__device__ bf16  g_Wol[Dm*Dm];
__device__ bf16  g_Wph[D2*D2];
__device__ bf16  g_Wpl[D2*D2];
__device__ bf16  g_Qb[(size_t)BH*NQ*DH];     // pre-scaled by SM_SCALE*LOG2E
__device__ bf16  g_Kb[(size_t)BH*NKEY*DH];
__device__ bf16  g_Vb[(size_t)BH*NKEY*DH];
__device__ bf16  g_Vp[(size_t)BH*NKP*40];    // [V/Z | 1/Z | 0-pad]
__device__ bf16  g_c2h[(size_t)Bz*NQ*Dm];
__device__ bf16  g_c2l[(size_t)Bz*NQ*Dm];
__device__ float g_tsh[BH*NQ];
__device__ float g_y0[(size_t)Bz*NQ*Dm];
__device__ bf16  g_ynh[(size_t)Bz*NQ*Dm];
__device__ bf16  g_ynl[(size_t)Bz*NQ*Dm];

// ---------------- mma helpers ----------------
__device__ __forceinline__ unsigned sm_addr(const void* p) {
    return (unsigned)__cvta_generic_to_shared(p);
}
__device__ __forceinline__ void ldsm4(unsigned r[4], const bf16* p) {
    unsigned a = sm_addr(p);
    asm volatile("ldmatrix.sync.aligned.m8n8.x4.shared.b16 {%0,%1,%2,%3},[%4];\n"
        : "=r"(r[0]),"=r"(r[1]),"=r"(r[2]),"=r"(r[3]) : "r"(a));
}
__device__ __forceinline__ void ldsm4t(unsigned r[4], const bf16* p) {
    unsigned a = sm_addr(p);
    asm volatile("ldmatrix.sync.aligned.m8n8.x4.trans.shared.b16 {%0,%1,%2,%3},[%4];\n"
        : "=r"(r[0]),"=r"(r[1]),"=r"(r[2]),"=r"(r[3]) : "r"(a));
}
__device__ __forceinline__ void ldsm2t(unsigned r[2], const bf16* p) {
    unsigned a = sm_addr(p);
    asm volatile("ldmatrix.sync.aligned.m8n8.x2.trans.shared.b16 {%0,%1},[%2];\n"
        : "=r"(r[0]),"=r"(r[1]) : "r"(a));
}
__device__ __forceinline__ void mma_bf16(float c[4], const unsigned a[4], unsigned b0, unsigned b1) {
    asm volatile("mma.sync.aligned.m16n8k16.row.col.f32.bf16.bf16.f32 "
        "{%0,%1,%2,%3},{%4,%5,%6,%7},{%8,%9},{%0,%1,%2,%3};\n"
        : "+f"(c[0]),"+f"(c[1]),"+f"(c[2]),"+f"(c[3])
        : "r"(a[0]),"r"(a[1]),"r"(a[2]),"r"(a[3]),"r"(b0),"r"(b1));
}
__device__ __forceinline__ unsigned packbf(float a, float b) {
    __nv_bfloat162 h = __floats2bfloat162_rn(a, b);
    return *reinterpret_cast<unsigned*>(&h);
}
__device__ __forceinline__ const bf16* lm(const bf16* base, int lane, int stride) {
    return base + (lane & 15) * stride + (lane >> 4) * 8;
}

// ---------------- small utils ----------------
__global__ void cvt_kernel(const float* __restrict__ s, bf16* __restrict__ d, int n) {
    int i = blockIdx.x * 256 + threadIdx.x;
    if (i < n) d[i] = __float2bfloat16(s[i]);
}
__global__ void cvt_split_kernel(const float* __restrict__ s,
                                 bf16* __restrict__ dh, bf16* __restrict__ dl, int n) {
    int i = blockIdx.x * 256 + threadIdx.x;
    if (i < n) {
        float v = s[i];
        bf16 h = __float2bfloat16(v);
        dh[i] = h;
        dl[i] = __float2bfloat16(v - __bfloat162float(h));
    }
}

template<typename OT>
__global__ void ln_kernel(const float* __restrict__ x, const float* __restrict__ g,
                          OT* __restrict__ y, int d)
{
    int row = blockIdx.x;
    int tid = threadIdx.x;
    const float* xr = x + (size_t)row * d;
    float s = 0.f, s2 = 0.f;
    for (int i = tid; i < d; i += 128) { float v = xr[i]; s += v; s2 += v * v; }
    __shared__ float sh[64];
    #pragma unroll
    for (int o = 16; o; o >>= 1) {
        s  += __shfl_xor_sync(0xffffffffu, s,  o);
        s2 += __shfl_xor_sync(0xffffffffu, s2, o);
    }
    int w = tid >> 5;
    if ((tid & 31) == 0) { sh[w] = s; sh[32 + w] = s2; }
    __syncthreads();
    if (tid == 0) {
        float a = 0.f, b = 0.f;
        #pragma unroll
        for (int i = 0; i < 4; i++) { a += sh[i]; b += sh[32 + i]; }
        sh[0] = a; sh[32] = b;
    }
    __syncthreads();
    float mu  = sh[0]  / (float)d;
    float var = sh[32] / (float)d - mu * mu;
    float r = rsqrtf(var + 1e-6f);
    OT* yr = y + (size_t)row * d;
    for (int i = tid; i < d; i += 128) yr[i] = (OT)((xr[i] - mu) * r * g[i]);
}

// LN with split hi/lo bf16 output
__global__ void ln_split_kernel(const float* __restrict__ x, const float* __restrict__ g,
                                bf16* __restrict__ yh, bf16* __restrict__ yl, int d)
{
    int row = blockIdx.x;
    int tid = threadIdx.x;
    const float* xr = x + (size_t)row * d;
    float s = 0.f, s2 = 0.f;
    for (int i = tid; i < d; i += 128) { float v = xr[i]; s += v; s2 += v * v; }
    __shared__ float sh[64];
    #pragma unroll
    for (int o = 16; o; o >>= 1) {
        s  += __shfl_xor_sync(0xffffffffu, s,  o);
        s2 += __shfl_xor_sync(0xffffffffu, s2, o);
    }
    int w = tid >> 5;
    if ((tid & 31) == 0) { sh[w] = s; sh[32 + w] = s2; }
    __syncthreads();
    if (tid == 0) {
        float a = 0.f, b = 0.f;
        #pragma unroll
        for (int i = 0; i < 4; i++) { a += sh[i]; b += sh[32 + i]; }
        sh[0] = a; sh[32] = b;
    }
    __syncthreads();
    float mu  = sh[0]  / (float)d;
    float var = sh[32] / (float)d - mu * mu;
    float r = rsqrtf(var + 1e-6f);
    for (int i = tid; i < d; i += 128) {
        float v = (xr[i] - mu) * r * g[i];
        bf16 h = __float2bfloat16(v);
        yh[(size_t)row * d + i] = h;
        yl[(size_t)row * d + i] = __float2bfloat16(v - __bfloat162float(h));
    }
}

// ---------------- bf16 HMMA projection GEMM (plain) ----------------
// MODE 0: scatter Q (pre-scaled by SM_SCALE*LOG2E)   MODE 1: scatter K/V
template<int MODE>
__global__ void __launch_bounds__(256)
bgemm(const bf16* __restrict__ A, const bf16* __restrict__ Bm, int M, int N, int K)
{
    __shared__ bf16 As[128 * 40];
    __shared__ bf16 Bs[32 * 136];
    const int tid = threadIdx.x;
    const int w = tid >> 5, lane = tid & 31;
    const int wm = w >> 1, wn = w & 1;
    const int m0 = blockIdx.y * 128, n0 = blockIdx.x * 128;

    float acc[2][8][4];
    #pragma unroll
    for (int i = 0; i < 2; i++)
        #pragma unroll
        for (int j = 0; j < 8; j++)
            #pragma unroll
            for (int t = 0; t < 4; t++) acc[i][j][t] = 0.f;

    for (int k0 = 0; k0 < K; k0 += 32) {
        #pragma unroll
        for (int i = 0; i < 2; i++) {
            int idx = tid + 256 * i;
            int row = idx >> 2, col = (idx & 3) * 8;
            uint4 v = *reinterpret_cast<const uint4*>(A + (size_t)(m0 + row) * K + k0 + col);
            *reinterpret_cast<uint4*>(&As[row * 40 + col]) = v;
        }
        #pragma unroll
        for (int i = 0; i < 2; i++) {
            int idx = tid + 256 * i;
            int row = idx >> 4, col = (idx & 15) * 8;
            uint4 v = *reinterpret_cast<const uint4*>(Bm + (size_t)(k0 + row) * N + n0 + col);
            *reinterpret_cast<uint4*>(&Bs[row * 136 + col]) = v;
        }
        __syncthreads();
        #pragma unroll
        for (int kc = 0; kc < 2; kc++) {
            unsigned af[2][4];
            ldsm4(af[0], lm(&As[(wm * 32 + 0)  * 40 + kc * 16], lane, 40));
            ldsm4(af[1], lm(&As[(wm * 32 + 16) * 40 + kc * 16], lane, 40));
            #pragma unroll
            for (int p = 0; p < 4; p++) {
                unsigned bfr[4];
                ldsm4t(bfr, lm(&Bs[(kc * 16) * 136 + wn * 64 + p * 16], lane, 136));
                #pragma unroll
                for (int mt = 0; mt < 2; mt++) {
                    mma_bf16(acc[mt][2 * p + 0], af[mt], bfr[0], bfr[1]);
                    mma_bf16(acc[mt][2 * p + 1], af[mt], bfr[2], bfr[3]);
                }
            }
        }
        __syncthreads();
    }

    #pragma unroll
    for (int mt = 0; mt < 2; mt++) {
        #pragma unroll
        for (int half = 0; half < 2; half++) {
            int gr = m0 + wm * 32 + mt * 16 + (lane >> 2) + half * 8;
            #pragma unroll
            for (int nb = 0; nb < 8; nb++) {
                int gc = n0 + wn * 64 + nb * 8 + (lane & 3) * 2;
                float v0 = acc[mt][nb][half * 2 + 0];
                float v1 = acc[mt][nb][half * 2 + 1];
                if (MODE == 0) {
                    int b = gr / NQ, q = gr - b * NQ;
                    int hh = gc >> 5, di = gc & 31;
                    __nv_bfloat162 hv = __floats2bfloat162_rn(v0 * (SM_SCALE * LOG2E),
                                                              v1 * (SM_SCALE * LOG2E));
                    *reinterpret_cast<__nv_bfloat162*>(
                        &g_Qb[(((size_t)(b * Hh + hh)) * NQ + q) * DH + di]) = hv;
                } else {
                    int b = gr / NKEY, k = gr - b * NKEY;
                    int two = gc >= Dm;
                    int cc = gc - two * Dm;
                    int hh = cc >> 5, di = cc & 31;
                    bf16* dst = two ? g_Vb : g_Kb;
                    __nv_bfloat162 hv = __floats2bfloat162_rn(v0, v1);
                    *reinterpret_cast<__nv_bfloat162*>(
                        &dst[(((size_t)(b * Hh + hh)) * NKEY + k) * DH + di]) = hv;
                }
            }
        }
    }
}

// ---------------- split-bf16 compensated GEMM: C = A@B (~fp32 accuracy) ----------------
// MODE 2: + res*rscale epilogue -> fp32   MODE 3: plain -> fp32
template<int MODE>
__global__ void __launch_bounds__(256)
bgemm_split(const bf16* __restrict__ Ah, const bf16* __restrict__ Al,
            const bf16* __restrict__ Bh, const bf16* __restrict__ Bl,
            int M, int N, int K,
            const float* __restrict__ res, const float* __restrict__ rscale,
            float* __restrict__ Cout)
{
    __shared__ bf16 Ash[128 * 40];
    __shared__ bf16 Asl[128 * 40];
    __shared__ bf16 Bsh[32 * 136];
    __shared__ bf16 Bsl[32 * 136];
    const int tid = threadIdx.x;
    const int w = tid >> 5, lane = tid & 31;
    const int wm = w >> 1, wn = w & 1;
    const int m0 = blockIdx.y * 128, n0 = blockIdx.x * 128;

    float acc[2][8][4];
    #pragma unroll
    for (int i = 0; i < 2; i++)
        #pragma unroll
        for (int j = 0; j < 8; j++)
            #pragma unroll
            for (int t = 0; t < 4; t++) acc[i][j][t] = 0.f;

    for (int k0 = 0; k0 < K; k0 += 32) {
        #pragma unroll
        for (int i = 0; i < 2; i++) {
            int idx = tid + 256 * i;
            int row = idx >> 2, col = (idx & 3) * 8;
            int gr = m0 + row;
            uint4 vh = make_uint4(0, 0, 0, 0), vl = make_uint4(0, 0, 0, 0);
            if (gr < M) {
                vh = *reinterpret_cast<const uint4*>(Ah + (size_t)gr * K + k0 + col);
                vl = *reinterpret_cast<const uint4*>(Al + (size_t)gr * K + k0 + col);
            }
            *reinterpret_cast<uint4*>(&Ash[row * 40 + col]) = vh;
            *reinterpret_cast<uint4*>(&Asl[row * 40 + col]) = vl;
        }
        #pragma unroll
        for (int i = 0; i < 2; i++) {
            int idx = tid + 256 * i;
            int row = idx >> 4, col = (idx & 15) * 8;
            *reinterpret_cast<uint4*>(&Bsh[row * 136 + col]) =
                *reinterpret_cast<const uint4*>(Bh + (size_t)(k0 + row) * N + n0 + col);
            *reinterpret_cast<uint4*>(&Bsl[row * 136 + col]) =
                *reinterpret_cast<const uint4*>(Bl + (size_t)(k0 + row) * N + n0 + col);
        }
        __syncthreads();
        #pragma unroll
        for (int kc = 0; kc < 2; kc++) {
            unsigned ah[2][4], al[2][4];
            ldsm4(ah[0], lm(&Ash[(wm * 32 + 0)  * 40 + kc * 16], lane, 40));
            ldsm4(ah[1], lm(&Ash[(wm * 32 + 16) * 40 + kc * 16], lane, 40));
            ldsm4(al[0], lm(&Asl[(wm * 32 + 0)  * 40 + kc * 16], lane, 40));
            ldsm4(al[1], lm(&Asl[(wm * 32 + 16) * 40 + kc * 16], lane, 40));
            #pragma unroll
            for (int p = 0; p < 4; p++) {
                unsigned bh[4], bl[4];
                ldsm4t(bh, lm(&Bsh[(kc * 16) * 136 + wn * 64 + p * 16], lane, 136));
                ldsm4t(bl, lm(&Bsl[(kc * 16) * 136 + wn * 64 + p * 16], lane, 136));
                #pragma unroll
                for (int mt = 0; mt < 2; mt++) {
                    mma_bf16(acc[mt][2 * p + 0], ah[mt], bh[0], bh[1]);
                    mma_bf16(acc[mt][2 * p + 1], ah[mt], bh[2], bh[3]);
                    mma_bf16(acc[mt][2 * p + 0], ah[mt], bl[0], bl[1]);
                    mma_bf16(acc[mt][2 * p + 1], ah[mt], bl[2], bl[3]);
                    mma_bf16(acc[mt][2 * p + 0], al[mt], bh[0], bh[1]);
                    mma_bf16(acc[mt][2 * p + 1], al[mt], bh[2], bh[3]);
                }
            }
        }
        __syncthreads();
    }

    #pragma unroll
    for (int mt = 0; mt < 2; mt++) {
        #pragma unroll
        for (int half = 0; half < 2; half++) {
            int gr = m0 + wm * 32 + mt * 16 + (lane >> 2) + half * 8;
            if (gr >= M) continue;
            #pragma unroll
            for (int nb = 0; nb < 8; nb++) {
                int gc = n0 + wn * 64 + nb * 8 + (lane & 3) * 2;
                float v0 = acc[mt][nb][half * 2 + 0];
                float v1 = acc[mt][nb][half * 2 + 1];
                if (MODE == 2) {
                    v0 += res[(size_t)gr * N + gc + 0] * rscale[gc + 0];
                    v1 += res[(size_t)gr * N + gc + 1] * rscale[gc + 1];
                }
                *reinterpret_cast<float2*>(&Cout[(size_t)gr * N + gc]) = make_float2(v0, v1);
            }
        }
    }
}

// ---------------- Z-pass ----------------
__global__ void __launch_bounds__(256)
zpass()
{
    __shared__ bf16 Ks[128 * 40];
    __shared__ bf16 Qs[128 * 40];
    __shared__ float zsh[128];
    const int tid = threadIdx.x;
    const int w = tid >> 5, lane = tid & 31;
    const int k0 = blockIdx.x * 128;
    const int bh = blockIdx.y;

    #pragma unroll
    for (int i = 0; i < 2; i++) {
        int idx = tid + 256 * i;
        int row = idx >> 2, col = (idx & 3) * 8;
        uint4 v = make_uint4(0, 0, 0, 0);
        int kg = k0 + row;
        if (kg < NKEY) v = *reinterpret_cast<const uint4*>(&g_Kb[((size_t)bh * NKEY + kg) * DH + col]);
        *reinterpret_cast<uint4*>(&Ks[row * 40 + col]) = v;
    }
    __syncthreads();

    unsigned aK[2][4];
    ldsm4(aK[0], lm(&Ks[(w * 16) * 40 + 0],  lane, 40));
    ldsm4(aK[1], lm(&Ks[(w * 16) * 40 + 16], lane, 40));

    float zacc[2] = {0.f, 0.f};

    for (int qc = 0; qc < 13; qc++) {
        __syncthreads();
        int q0 = qc * 128;
        #pragma unroll
        for (int i = 0; i < 2; i++) {
            int idx = tid + 256 * i;
            int row = idx >> 2, col = (idx & 3) * 8;
            uint4 v = make_uint4(0, 0, 0, 0);
            int qg = q0 + row;
            if (qg < NQ) v = *reinterpret_cast<const uint4*>(&g_Qb[((size_t)bh * NQ + qg) * DH + col]);
            *reinterpret_cast<uint4*>(&Qs[row * 40 + col]) = v;
        }
        __syncthreads();
        #pragma unroll
        for (int nb2 = 0; nb2 < 8; nb2++) {
            unsigned bA[4], bB[4];
            ldsm4(bA, lm(&Qs[(nb2 * 16) * 40 + 0],  lane, 40));
            ldsm4(bB, lm(&Qs[(nb2 * 16) * 40 + 16], lane, 40));
            #pragma unroll
            for (int s = 0; s < 2; s++) {
                float c[4] = {0.f, 0.f, 0.f, 0.f};
                mma_bf16(c, aK[0], bA[s], bA[s + 2]);
                mma_bf16(c, aK[1], bB[s], bB[s + 2]);
                #pragma unroll
                for (int j = 0; j < 4; j++) {
                    int col = nb2 * 16 + s * 8 + (lane & 3) * 2 + (j & 1);
                    if (q0 + col < NQ) zacc[j >> 1] += exp2f(c[j]);
                }
            }
        }
    }

    #pragma unroll
    for (int i = 0; i < 2; i++) {
        zacc[i] += __shfl_xor_sync(0xffffffffu, zacc[i], 1);
        zacc[i] += __shfl_xor_sync(0xffffffffu, zacc[i], 2);
    }
    if ((lane & 3) == 0) {
        zsh[w * 16 + (lane >> 2)]     = zacc[0];
        zsh[w * 16 + 8 + (lane >> 2)] = zacc[1];
    }
    __syncthreads();

    if (tid < 128) {
        int kg = k0 + tid;
        bf16 outr[40];
        if (kg < NKEY) {
            float iz = 1.f / zsh[tid];
            const bf16* vr = &g_Vb[((size_t)bh * NKEY + kg) * DH];
            #pragma unroll
            for (int j = 0; j < 32; j++) outr[j] = __float2bfloat16(__bfloat162float(vr[j]) * iz);
            outr[32] = __float2bfloat16(iz);
            #pragma unroll
            for (int j = 33; j < 40; j++) outr[j] = __float2bfloat16(0.f);
        } else {
            #pragma unroll
            for (int j = 0; j < 40; j++) outr[j] = __float2bfloat16(0.f);
        }
        bf16* dst = &g_Vp[((size_t)bh * NKP + k0 + tid) * 40];
        #pragma unroll
        for (int j = 0; j < 5; j++)
            *reinterpret_cast<uint4*>(dst + j * 8) = *reinterpret_cast<const uint4*>(outr + j * 8);
    }
}

// ---------------- PV-pass ----------------
__global__ void __launch_bounds__(256)
pvpass()
{
    __shared__ bf16 Qs[128 * 40];
    __shared__ bf16 Ks[128 * 40];
    __shared__ bf16 Vs[128 * 40];
    const int tid = threadIdx.x;
    const int w = tid >> 5, lane = tid & 31;
    const int q0 = blockIdx.x * 128;
    const int bh = blockIdx.y;
    const int b = bh / Hh, hh = bh % Hh;

    #pragma unroll
    for (int i = 0; i < 2; i++) {
        int idx = tid + 256 * i;
        int row = idx >> 2, col = (idx & 3) * 8;
        uint4 v = make_uint4(0, 0, 0, 0);
        int qg = q0 + row;
        if (qg < NQ) v = *reinterpret_cast<const uint4*>(&g_Qb[((size_t)bh * NQ + qg) * DH + col]);
        *reinterpret_cast<uint4*>(&Qs[row * 40 + col]) = v;
    }
    __syncthreads();

    unsigned aQ[2][4];
    ldsm4(aQ[0], lm(&Qs[(w * 16) * 40 + 0],  lane, 40));
    ldsm4(aQ[1], lm(&Qs[(w * 16) * 40 + 16], lane, 40));

    float acc[5][4];
    #pragma unroll
    for (int i = 0; i < 5; i++)
        #pragma unroll
        for (int t = 0; t < 4; t++) acc[i][t] = 0.f;

    for (int kt = 0; kt < 25; kt++) {
        int k0 = kt * 128;
        __syncthreads();
        #pragma unroll
        for (int i = 0; i < 2; i++) {
            int idx = tid + 256 * i;
            int row = idx >> 2, col = (idx & 3) * 8;
            uint4 v = make_uint4(0, 0, 0, 0);
            int kg = k0 + row;
            if (kg < NKEY) v = *reinterpret_cast<const uint4*>(&g_Kb[((size_t)bh * NKEY + kg) * DH + col]);
            *reinterpret_cast<uint4*>(&Ks[row * 40 + col]) = v;
        }
        #pragma unroll
        for (int i = 0; i < 3; i++) {
            int idx = tid + 256 * i;
            if (idx < 640) {
                int row = idx / 5, col = (idx % 5) * 8;
                uint4 v = *reinterpret_cast<const uint4*>(&g_Vp[((size_t)bh * NKP + k0 + row) * 40 + col]);
                *reinterpret_cast<uint4*>(&Vs[row * 40 + col]) = v;
            }
        }
        __syncthreads();

        unsigned pa[8][4];
        #pragma unroll
        for (int nb2 = 0; nb2 < 8; nb2++) {
            unsigned bA[4], bB[4];
            ldsm4(bA, lm(&Ks[(nb2 * 16) * 40 + 0],  lane, 40));
            ldsm4(bB, lm(&Ks[(nb2 * 16) * 40 + 16], lane, 40));
            float c0[4] = {0.f, 0.f, 0.f, 0.f};
            float c1[4] = {0.f, 0.f, 0.f, 0.f};
            mma_bf16(c0, aQ[0], bA[0], bA[2]);
            mma_bf16(c0, aQ[1], bB[0], bB[2]);
            mma_bf16(c1, aQ[0], bA[1], bA[3]);
            mma_bf16(c1, aQ[1], bB[1], bB[3]);
            pa[nb2][0] = packbf(exp2f(c0[0]), exp2f(c0[1]));
            pa[nb2][1] = packbf(exp2f(c0[2]), exp2f(c0[3]));
            pa[nb2][2] = packbf(exp2f(c1[0]), exp2f(c1[1]));
            pa[nb2][3] = packbf(exp2f(c1[2]), exp2f(c1[3]));
        }
        #pragma unroll
        for (int kc = 0; kc < 8; kc++) {
            unsigned v0[4], v1[4], v2[2];
            ldsm4t(v0, lm(&Vs[(kc * 16) * 40 + 0],  lane, 40));
            ldsm4t(v1, lm(&Vs[(kc * 16) * 40 + 16], lane, 40));
            ldsm2t(v2, lm(&Vs[(kc * 16) * 40 + 32], lane, 40));
            mma_bf16(acc[0], pa[kc], v0[0], v0[1]);
            mma_bf16(acc[1], pa[kc], v0[2], v0[3]);
            mma_bf16(acc[2], pa[kc], v1[0], v1[1]);
            mma_bf16(acc[3], pa[kc], v1[2], v1[3]);
            mma_bf16(acc[4], pa[kc], v2[0], v2[1]);
        }
    }

    int src = lane & 28;
    float den0 = __shfl_sync(0xffffffffu, acc[4][0], src);
    float den1 = __shfl_sync(0xffffffffu, acc[4][2], src);
    float inv0 = 1.f / (den0 + 1e-6f);
    float inv1 = 1.f / (den1 + 1e-6f);

    int qr0 = q0 + w * 16 + (lane >> 2);
    int qr1 = qr0 + 8;
    if (qr0 < NQ) {
        size_t base = ((size_t)b * NQ + qr0) * Dm + hh * DH + (lane & 3) * 2;
        #pragma unroll
        for (int nb = 0; nb < 4; nb++) {
            float v0 = acc[nb][0] * inv0, v1 = acc[nb][1] * inv0;
            __nv_bfloat162 h = __floats2bfloat162_rn(v0, v1);
            __nv_bfloat162 l = __floats2bfloat162_rn(v0 - __bfloat162float(__low2bfloat16(h)),
                                                     v1 - __bfloat162float(__high2bfloat16(h)));
            *reinterpret_cast<__nv_bfloat162*>(&g_c2h[base + nb * 8]) = h;
            *reinterpret_cast<__nv_bfloat162*>(&g_c2l[base + nb * 8]) = l;
        }
        if ((lane & 3) == 0) g_tsh[(size_t)bh * NQ + qr0] = den0;
    }
    if (qr1 < NQ) {
        size_t base = ((size_t)b * NQ + qr1) * Dm + hh * DH + (lane & 3) * 2;
        #pragma unroll
        for (int nb = 0; nb < 4; nb++) {
            float v0 = acc[nb][2] * inv1, v1 = acc[nb][3] * inv1;
            __nv_bfloat162 h = __floats2bfloat162_rn(v0, v1);
            __nv_bfloat162 l = __floats2bfloat162_rn(v0 - __bfloat162float(__low2bfloat16(h)),
                                                     v1 - __bfloat162float(__high2bfloat16(h)));
            *reinterpret_cast<__nv_bfloat162*>(&g_c2h[base + nb * 8]) = h;
            *reinterpret_cast<__nv_bfloat162*>(&g_c2l[base + nb * 8]) = l;
        }
        if ((lane & 3) == 0) g_tsh[(size_t)bh * NQ + qr1] = den1;
    }
}

// ---------------- token sizes output ----------------
__global__ void ts_kernel(float* __restrict__ out)
{
    int idx = blockIdx.x * 256 + threadIdx.x;
    if (idx >= Bz * NP) return;
    int b = idx / NP, p = idx % NP;
    float s = 0.f;
    #pragma unroll
    for (int h = 0; h < Hh; h++) {
        const float* t = g_tsh + ((size_t)(b * Hh + h)) * NQ + 2 * p;
        s += t[0] + t[1];
    }
    out[idx] = s * (1.f / 12.f);
}

// ---------------- launch ----------------
extern "C" void kernel_launch(void* const* d_in, const int* in_sizes, int n_in,
                              void* d_out, int out_size)
{
    const float* x         = (const float*)d_in[0];
    const float* clusters  = (const float*)d_in[1];
    const float* g1        = (const float*)d_in[2];
    const float* Wq        = (const float*)d_in[3];
    const float* Wkv       = (const float*)d_in[4];
    const float* Wo        = (const float*)d_in[5];
    const float* res_scale = (const float*)d_in[6];
    const float* g2        = (const float*)d_in[7];
    const float* Wproj     = (const float*)d_in[8];
    float* out = (float*)d_out;

    bf16 *p_xnb, *p_cnb, *p_Wqb, *p_Wkvb, *p_Woh, *p_Wol, *p_Wph, *p_Wpl;
    bf16 *p_c2h, *p_c2l, *p_ynh, *p_ynl;
    float *p_y0;
    cudaGetSymbolAddress((void**)&p_xnb, g_xnb);
    cudaGetSymbolAddress((void**)&p_cnb, g_cnb);
    cudaGetSymbolAddress((void**)&p_Wqb, g_Wqb);
    cudaGetSymbolAddress((void**)&p_Wkvb, g_Wkvb);
    cudaGetSymbolAddress((void**)&p_Woh, g_Woh);
    cudaGetSymbolAddress((void**)&p_Wol, g_Wol);
    cudaGetSymbolAddress((void**)&p_Wph, g_Wph);
    cudaGetSymbolAddress((void**)&p_Wpl, g_Wpl);
    cudaGetSymbolAddress((void**)&p_c2h, g_c2h);
    cudaGetSymbolAddress((void**)&p_c2l, g_c2l);
    cudaGetSymbolAddress((void**)&p_ynh, g_ynh);
    cudaGetSymbolAddress((void**)&p_ynl, g_ynl);
    cudaGetSymbolAddress((void**)&p_y0, g_y0);

    // weight conversions
    cvt_kernel<<<(Dm * Dm + 255) / 256, 256>>>(Wq, p_Wqb, Dm * Dm);
    cvt_kernel<<<(Dm * 2 * Dm + 255) / 256, 256>>>(Wkv, p_Wkvb, Dm * 2 * Dm);
    cvt_split_kernel<<<(Dm * Dm + 255) / 256, 256>>>(Wo, p_Woh, p_Wol, Dm * Dm);
    cvt_split_kernel<<<(D2 * D2 + 255) / 256, 256>>>(Wproj, p_Wph, p_Wpl, D2 * D2);

    // LayerNorms
    ln_kernel<bf16><<<Bz * NKEY, 128>>>(x,        g1, p_xnb, Dm);
    ln_kernel<bf16><<<Bz * NQ,   128>>>(clusters, g1, p_cnb, Dm);

    // projections (bf16 tensor core)
    bgemm<0><<<dim3(3, 49), 256>>>(p_cnb, p_Wqb,  Bz * NQ,   Dm,     Dm);
    bgemm<1><<<dim3(6, 98), 256>>>(p_xnb, p_Wkvb, Bz * NKEY, 2 * Dm, Dm);

    // attention
    zpass<<<dim3(25, BH), 256>>>();
    pvpass<<<dim3(13, BH), 256>>>();

    // output path: split-bf16 compensated tensor-core GEMMs
    bgemm_split<2><<<dim3(3, 49), 256>>>(p_c2h, p_c2l, p_Woh, p_Wol,
                                         Bz * NQ, Dm, Dm, clusters, res_scale, p_y0);
    ln_split_kernel<<<Bz * NP, 128>>>(p_y0, g2, p_ynh, p_ynl, D2);
    bgemm_split<3><<<dim3(6, 25), 256>>>(p_ynh, p_ynl, p_Wph, p_Wpl,
                                         Bz * NP, D2, D2, nullptr, nullptr, out);

    ts_kernel<<<(Bz * NP + 255) / 256, 256>>>(out + (size_t)Bz * NP * D2);
}